// round 13
// baseline (speedup 1.0000x reference)
#include <cuda_runtime.h>
#include <cuda_fp16.h>
#include <math.h>
#include <stdint.h>

// HashEmbedder: 16-level 2D multires hash grid, 2 feats/level, T=2^19.
// Phase 1: build fp16 cell-packed corner table (16B per cell).
// Phase 2: persistent, full-occupancy kernel. Levels 0-3 (2705 cells,
// 43.3KB) served from SMEM via the shared crossbar (separate structural
// path from LDG line fetch); levels 4-7 via __ldg (L1); 8-15 via ld.cg (L2).

#define NLEV 16
#define TLOG2 19
#define TSIZE (1u << TLOG2)
#define HMASK ((1u << TLOG2) - 1u)
#define PRIME1 2654435761u

#define SMEM_LEVELS 4            // levels 0..3 in shared memory
#define SMEM_CELLS  2705         // 16^2+20^2+25^2+32^2

// Sum of res^2 over the 16 levels = 706,816 cells; margin for safety.
#define MAX_CELLS 710000
__device__ uint4 g_packed[MAX_CELLS];   // 16B per cell: h00,h10,h01,h11

struct Params {
    float resF[NLEV];
    int   resI[NLEV];
    int   off[NLEV];
    int   total;
};

// ---------------------------------------------------------------------------
// Phase 1: build packed table. One thread per cell.
// ---------------------------------------------------------------------------
__global__ __launch_bounds__(256) void build_packed_kernel(
    const float* __restrict__ emb, Params pm, int total_cells)
{
    int i = blockIdx.x * blockDim.x + threadIdx.x;
    if (i >= total_cells) return;

    int l = 0;
#pragma unroll
    for (int k = 1; k < NLEV; ++k) l += (i >= pm.off[k]);

    int c   = i - pm.off[l];
    int res = pm.resI[l];
    int cy  = c / res;
    int cx  = c - cy * res;

    uint32_t ux0 = (uint32_t)cx;
    uint32_t ux1 = (uint32_t)(cx + 1);
    uint32_t yp0 = (uint32_t)cy * PRIME1;
    uint32_t yp1 = (uint32_t)(cy + 1) * PRIME1;

    uint32_t a00 = (ux0 ^ yp0) & HMASK;
    uint32_t a10 = (ux1 ^ yp0) & HMASK;
    uint32_t a01 = (ux0 ^ yp1) & HMASK;
    uint32_t a11 = (ux1 ^ yp1) & HMASK;

    const float2* __restrict__ tab =
        ((const float2*)emb) + ((size_t)l << TLOG2);

    float2 f00 = __ldg(tab + a00);
    float2 f10 = __ldg(tab + a10);
    float2 f01 = __ldg(tab + a01);
    float2 f11 = __ldg(tab + a11);

    half2 h00 = __float22half2_rn(f00);
    half2 h10 = __float22half2_rn(f10);
    half2 h01 = __float22half2_rn(f01);
    half2 h11 = __float22half2_rn(f11);

    uint4 r;
    r.x = *(const uint32_t*)&h00;
    r.y = *(const uint32_t*)&h10;
    r.z = *(const uint32_t*)&h01;
    r.w = *(const uint32_t*)&h11;
    g_packed[i] = r;
}

// ---------------------------------------------------------------------------
// Phase 2: persistent; levels 0-3 from SMEM, 4-7 from L1, 8-15 from L2.
// ---------------------------------------------------------------------------
#define BLK 512
#define PPB (BLK / 4)            // 128 points per block-iteration

__global__ __launch_bounds__(BLK, 4) void hash_embed_kernel(
    const float* __restrict__ x,
    float* __restrict__ out,
    int n_points,
    Params pm)
{
    __shared__ uint4  s_cells[SMEM_CELLS];   // 43.3 KB: levels 0-3 records
    __shared__ float4 s_lv[NLEV];            // per-level params

    if (threadIdx.x < NLEV) {
        s_lv[threadIdx.x] = make_float4(
            pm.resF[threadIdx.x],
            __int_as_float(pm.resI[threadIdx.x]),
            __int_as_float(pm.off[threadIdx.x]),
            0.0f);
    }
    // Copy the coarse-table prefix (levels 0-3 occupy g_packed[0..2705)).
    for (int i = threadIdx.x; i < SMEM_CELLS; i += BLK)
        s_cells[i] = g_packed[i];
    __syncthreads();

    int tsub = threadIdx.x & 3;       // 4-level group: 0..3
    int lb   = tsub << 2;             // base level: 0,4,8,12
    int trow = threadIdx.x >> 2;      // point row within block

    for (int base = blockIdx.x * PPB; base < n_points; base += gridDim.x * PPB) {
        int p = base + trow;
        if (p < n_points) {
            float2 xy = __ldg(((const float2*)x) + p);

            int   idx[4];
            float wx[4], wy[4];
#pragma unroll
            for (int j = 0; j < 4; ++j) {
                float4 lv  = s_lv[lb + j];
                float  res = lv.x;
                int    ri  = __float_as_int(lv.y);
                int    off = __float_as_int(lv.z);

                float px = xy.x * res;
                float py = xy.y * res;
                float fx = floorf(px);
                float fy = floorf(py);
                wx[j] = px - fx;
                wy[j] = py - fy;

                int ix = min(max((int)fx, 0), ri - 1);
                int iy = min(max((int)fy, 0), ri - 1);
                idx[j] = off + iy * ri + ix;
            }

            uint4 rr[4];
            if (lb == 0) {
                // levels 0-3: SMEM crossbar (off[0..3] are 0-based prefix)
#pragma unroll
                for (int j = 0; j < 4; ++j) rr[j] = s_cells[idx[j]];
            } else if (lb == 4) {
                // levels 4-7 (~221KB): L1-cached
#pragma unroll
                for (int j = 0; j < 4; ++j) rr[j] = __ldg(&g_packed[idx[j]]);
            } else {
                // levels 8-15 (10.8MB): L2 only
#pragma unroll
                for (int j = 0; j < 4; ++j) {
                    uint4 v;
                    asm("ld.global.cg.v4.u32 {%0,%1,%2,%3}, [%4];"
                        : "=r"(v.x), "=r"(v.y), "=r"(v.z), "=r"(v.w)
                        : "l"(&g_packed[idx[j]]));
                    rr[j] = v;
                }
            }

            float o[8];
#pragma unroll
            for (int j = 0; j < 4; ++j) {
                float2 f00 = __half22float2(*(const half2*)&rr[j].x);
                float2 f10 = __half22float2(*(const half2*)&rr[j].y);
                float2 f01 = __half22float2(*(const half2*)&rr[j].z);
                float2 f11 = __half22float2(*(const half2*)&rr[j].w);

                float u = 1.0f - wx[j];
                float v = 1.0f - wy[j];

                o[2 * j]     = (f00.x * u + f10.x * wx[j]) * v + (f01.x * u + f11.x * wx[j]) * wy[j];
                o[2 * j + 1] = (f00.y * u + f10.y * wx[j]) * v + (f01.y * u + f11.y * wx[j]) * wy[j];
            }

            float4* dst = (float4*)(out + (size_t)p * (NLEV * 2) + lb * 2);
            dst[0] = make_float4(o[0], o[1], o[2], o[3]);
            dst[1] = make_float4(o[4], o[5], o[6], o[7]);
        }
    }
}

extern "C" void kernel_launch(void* const* d_in, const int* in_sizes, int n_in,
                              void* d_out, int out_size)
{
    const float* x   = (const float*)d_in[0];
    const float* emb = (const float*)d_in[1];
    float* out       = (float*)d_out;

    int n_points = in_sizes[0] / 2;

    Params pm;
    double b = exp((log(512.0) - log(16.0)) / 15.0);
    int acc = 0;
    for (int l = 0; l < NLEV; ++l) {
        double r = floor(16.0 * pow(b, (double)l));
        pm.resF[l] = (float)r;
        pm.resI[l] = (int)r;
        pm.off[l]  = acc;
        acc += pm.resI[l] * pm.resI[l];
    }
    pm.total = acc;

    // Phase 1: build packed corner table (fp16, 16B per cell)
    {
        int threads = 256;
        int blocks = (acc + threads - 1) / threads;
        build_packed_kernel<<<blocks, threads>>>(emb, pm, acc);
    }

    // Phase 2: persistent gather + lerp
    {
        static int nsm = 0;
        if (nsm == 0) {
            cudaDeviceGetAttribute(&nsm, cudaDevAttrMultiProcessorCount, 0);
            cudaFuncSetAttribute(hash_embed_kernel,
                                 cudaFuncAttributePreferredSharedMemoryCarveout,
                                 cudaSharedmemCarveoutMaxShared);
        }
        int blocks = nsm * 4;
        hash_embed_kernel<<<blocks, BLK>>>(x, out, n_points, pm);
    }
}

// round 14
// speedup vs baseline: 1.3907x; 1.3907x over previous
#include <cuda_runtime.h>
#include <cuda_fp16.h>
#include <math.h>
#include <stdint.h>

// HashEmbedder: 16-level 2D multires hash grid, 2 feats/level, T=2^19.
// Phase 1: build fp16 cell-packed corner table (16B per cell).
// Phase 2 (R5 shape): 4 thr/point, 4 levels/thread, MLP=4.
//   levels 0-6  (168KB < L1 w/ max carveout): __ldg -> L1-resident hits
//   levels 7-15 (10.9MB): ld.cg -> L2 only, no L1 fills/evictions
//   output: st.cs streaming stores -> don't evict table from L2
// Rationale: l1tex queue (~248 lines/SM) is the binder; L1 hits recycle
// queue slots at 39cyc vs 250cyc, decongesting the queue for L2 gathers.

#define NLEV 16
#define TLOG2 19
#define TSIZE (1u << TLOG2)
#define HMASK ((1u << TLOG2) - 1u)
#define PRIME1 2654435761u

// Sum of res^2 over the 16 levels = 706,816 cells; margin for safety.
#define MAX_CELLS 710000
__device__ uint4 g_packed[MAX_CELLS];   // 16B per cell: h00,h10,h01,h11

struct Params {
    float resF[NLEV];
    int   resI[NLEV];
    int   off[NLEV];
    int   total;
};

// ---------------------------------------------------------------------------
// Phase 1: build packed table. One thread per cell.
// ---------------------------------------------------------------------------
__global__ __launch_bounds__(256) void build_packed_kernel(
    const float* __restrict__ emb, Params pm, int total_cells)
{
    int i = blockIdx.x * blockDim.x + threadIdx.x;
    if (i >= total_cells) return;

    int l = 0;
#pragma unroll
    for (int k = 1; k < NLEV; ++k) l += (i >= pm.off[k]);

    int c   = i - pm.off[l];
    int res = pm.resI[l];
    int cy  = c / res;
    int cx  = c - cy * res;

    uint32_t ux0 = (uint32_t)cx;
    uint32_t ux1 = (uint32_t)(cx + 1);
    uint32_t yp0 = (uint32_t)cy * PRIME1;
    uint32_t yp1 = (uint32_t)(cy + 1) * PRIME1;

    uint32_t a00 = (ux0 ^ yp0) & HMASK;
    uint32_t a10 = (ux1 ^ yp0) & HMASK;
    uint32_t a01 = (ux0 ^ yp1) & HMASK;
    uint32_t a11 = (ux1 ^ yp1) & HMASK;

    const float2* __restrict__ tab =
        ((const float2*)emb) + ((size_t)l << TLOG2);

    float2 f00 = __ldg(tab + a00);
    float2 f10 = __ldg(tab + a10);
    float2 f01 = __ldg(tab + a01);
    float2 f11 = __ldg(tab + a11);

    half2 h00 = __float22half2_rn(f00);
    half2 h10 = __float22half2_rn(f10);
    half2 h01 = __float22half2_rn(f01);
    half2 h11 = __float22half2_rn(f11);

    uint4 r;
    r.x = *(const uint32_t*)&h00;
    r.y = *(const uint32_t*)&h10;
    r.z = *(const uint32_t*)&h01;
    r.w = *(const uint32_t*)&h11;
    g_packed[i] = r;
}

// ---------------------------------------------------------------------------
// Phase 2: one thread per (point, 4-level group). MLP=4 gathers.
// ---------------------------------------------------------------------------
__global__ __launch_bounds__(256) void hash_embed_kernel(
    const float* __restrict__ x,
    float* __restrict__ out,
    int n_points,
    Params pm)
{
    // One float4 per level: {resF, resI (bits), off (bits), 0}
    __shared__ float4 s_lv[NLEV];
    if (threadIdx.x < NLEV) {
        s_lv[threadIdx.x] = make_float4(
            pm.resF[threadIdx.x],
            __int_as_float(pm.resI[threadIdx.x]),
            __int_as_float(pm.off[threadIdx.x]),
            0.0f);
    }
    __syncthreads();

    int gid = blockIdx.x * blockDim.x + threadIdx.x;
    int p = gid >> 2;              // point index (4 threads per point)
    if (p >= n_points) return;
    int lb = (gid & 3) << 2;       // base level: 0,4,8,12

    // 4 consecutive threads read the same point -> broadcast load
    float2 xy = __ldg(((const float2*)x) + p);

    int   idx[4];
    float wx[4], wy[4];

#pragma unroll
    for (int j = 0; j < 4; ++j) {
        float4 lv  = s_lv[lb + j];       // single LDS.128
        float  res = lv.x;
        int    ri  = __float_as_int(lv.y);
        int    off = __float_as_int(lv.z);

        float px = xy.x * res;
        float py = xy.y * res;
        float fx = floorf(px);
        float fy = floorf(py);
        wx[j] = px - fx;
        wy[j] = py - fy;

        int ix = min(max((int)fx, 0), ri - 1);
        int iy = min(max((int)fy, 0), ri - 1);
        idx[j] = off + iy * ri + ix;
    }

    uint4 rr[4];
#pragma unroll
    for (int j = 0; j < 4; ++j) {
        if (lb + j < 7) {
            // levels 0-6 (168KB): L1-resident via default caching
            rr[j] = __ldg(&g_packed[idx[j]]);
        } else {
            // levels 7-15 (10.9MB): L2 only, no L1 fills/evictions
            uint4 v;
            asm("ld.global.cg.v4.u32 {%0,%1,%2,%3}, [%4];"
                : "=r"(v.x), "=r"(v.y), "=r"(v.z), "=r"(v.w)
                : "l"(&g_packed[idx[j]]));
            rr[j] = v;
        }
    }

    float o[8];
#pragma unroll
    for (int j = 0; j < 4; ++j) {
        float2 f00 = __half22float2(*(const half2*)&rr[j].x);
        float2 f10 = __half22float2(*(const half2*)&rr[j].y);
        float2 f01 = __half22float2(*(const half2*)&rr[j].z);
        float2 f11 = __half22float2(*(const half2*)&rr[j].w);

        float u = 1.0f - wx[j];
        float v = 1.0f - wy[j];

        o[2 * j]     = (f00.x * u + f10.x * wx[j]) * v + (f01.x * u + f11.x * wx[j]) * wy[j];
        o[2 * j + 1] = (f00.y * u + f10.y * wx[j]) * v + (f01.y * u + f11.y * wx[j]) * wy[j];
    }

    // out row = p*32 floats; this thread covers floats [lb*2, lb*2+8) = 32B.
    // 4 threads per point -> full 128B line. Streaming stores: evict-first,
    // keep the packed table resident in L2.
    float* dst = out + (size_t)p * (NLEV * 2) + lb * 2;
    asm volatile("st.global.cs.v4.f32 [%0], {%1,%2,%3,%4};"
                 :: "l"(dst), "f"(o[0]), "f"(o[1]), "f"(o[2]), "f"(o[3]));
    asm volatile("st.global.cs.v4.f32 [%0], {%1,%2,%3,%4};"
                 :: "l"(dst + 4), "f"(o[4]), "f"(o[5]), "f"(o[6]), "f"(o[7]));
}

extern "C" void kernel_launch(void* const* d_in, const int* in_sizes, int n_in,
                              void* d_out, int out_size)
{
    const float* x   = (const float*)d_in[0];
    const float* emb = (const float*)d_in[1];
    float* out       = (float*)d_out;

    int n_points = in_sizes[0] / 2;

    Params pm;
    double b = exp((log(512.0) - log(16.0)) / 15.0);
    int acc = 0;
    for (int l = 0; l < NLEV; ++l) {
        double r = floor(16.0 * pow(b, (double)l));
        pm.resF[l] = (float)r;
        pm.resI[l] = (int)r;
        pm.off[l]  = acc;
        acc += pm.resI[l] * pm.resI[l];
    }
    pm.total = acc;

    static bool configured = false;
    if (!configured) {
        // Maximize L1 carveout: phase-2 uses only 256B of SMEM.
        cudaFuncSetAttribute(hash_embed_kernel,
                             cudaFuncAttributePreferredSharedMemoryCarveout,
                             cudaSharedmemCarveoutMaxL1);
        configured = true;
    }

    // Phase 1: build packed corner table (fp16, 16B per cell)
    {
        int threads = 256;
        int blocks = (acc + threads - 1) / threads;
        build_packed_kernel<<<blocks, threads>>>(emb, pm, acc);
    }

    // Phase 2: gather + lerp, 4 threads per point
    {
        long long total = (long long)n_points * 4;
        int threads = 256;
        int blocks = (int)((total + threads - 1) / threads);
        hash_embed_kernel<<<blocks, threads>>>(x, out, n_points, pm);
    }
}

// round 15
// speedup vs baseline: 1.4168x; 1.0188x over previous
#include <cuda_runtime.h>
#include <cuda_fp16.h>
#include <math.h>
#include <stdint.h>

// HashEmbedder: 16-level 2D multires hash grid, 2 feats/level, T=2^19.
// Phase 1: build fp16 cell-packed corner table (16B per cell).
// Phase 2: PERSISTENT grid-stride, 4 thr/point, 4 levels/thread.
//   - level params hoisted to registers once per thread (no per-point LDS)
//   - unroll-2 loop lets ptxas overlap next point's loads with current lerp
//   - levels 0-6: __ldg (L1-resident, MaxL1 carveout); 7-15: ld.cg (L2)
//   - st.cs streaming stores

#define NLEV 16
#define TLOG2 19
#define TSIZE (1u << TLOG2)
#define HMASK ((1u << TLOG2) - 1u)
#define PRIME1 2654435761u

// Sum of res^2 over the 16 levels = 706,816 cells; margin for safety.
#define MAX_CELLS 710000
__device__ uint4 g_packed[MAX_CELLS];   // 16B per cell: h00,h10,h01,h11

struct Params {
    float resF[NLEV];
    int   resI[NLEV];
    int   off[NLEV];
    int   total;
};

// ---------------------------------------------------------------------------
// Phase 1: build packed table. One thread per cell.
// ---------------------------------------------------------------------------
__global__ __launch_bounds__(256) void build_packed_kernel(
    const float* __restrict__ emb, Params pm, int total_cells)
{
    int i = blockIdx.x * blockDim.x + threadIdx.x;
    if (i >= total_cells) return;

    int l = 0;
#pragma unroll
    for (int k = 1; k < NLEV; ++k) l += (i >= pm.off[k]);

    int c   = i - pm.off[l];
    int res = pm.resI[l];
    int cy  = c / res;
    int cx  = c - cy * res;

    uint32_t ux0 = (uint32_t)cx;
    uint32_t ux1 = (uint32_t)(cx + 1);
    uint32_t yp0 = (uint32_t)cy * PRIME1;
    uint32_t yp1 = (uint32_t)(cy + 1) * PRIME1;

    uint32_t a00 = (ux0 ^ yp0) & HMASK;
    uint32_t a10 = (ux1 ^ yp0) & HMASK;
    uint32_t a01 = (ux0 ^ yp1) & HMASK;
    uint32_t a11 = (ux1 ^ yp1) & HMASK;

    const float2* __restrict__ tab =
        ((const float2*)emb) + ((size_t)l << TLOG2);

    float2 f00 = __ldg(tab + a00);
    float2 f10 = __ldg(tab + a10);
    float2 f01 = __ldg(tab + a01);
    float2 f11 = __ldg(tab + a11);

    half2 h00 = __float22half2_rn(f00);
    half2 h10 = __float22half2_rn(f10);
    half2 h01 = __float22half2_rn(f01);
    half2 h11 = __float22half2_rn(f11);

    uint4 r;
    r.x = *(const uint32_t*)&h00;
    r.y = *(const uint32_t*)&h10;
    r.z = *(const uint32_t*)&h01;
    r.w = *(const uint32_t*)&h11;
    g_packed[i] = r;
}

// ---------------------------------------------------------------------------
// Phase 2: persistent grid-stride; 4 threads per point, 4 levels/thread.
// ---------------------------------------------------------------------------
__global__ __launch_bounds__(256, 5) void hash_embed_kernel(
    const float* __restrict__ x,
    float* __restrict__ out,
    int n_points,
    Params pm)
{
    __shared__ float4 s_lv[NLEV];
    if (threadIdx.x < NLEV) {
        s_lv[threadIdx.x] = make_float4(
            pm.resF[threadIdx.x],
            __int_as_float(pm.resI[threadIdx.x]),
            __int_as_float(pm.off[threadIdx.x]),
            0.0f);
    }
    __syncthreads();

    int gid = blockIdx.x * blockDim.x + threadIdx.x;
    int lb  = (gid & 3) << 2;      // base level: 0,4,8,12 (fixed per thread)

    // Hoist this thread's 4 level-param triples into registers (once).
    float resF[4];
    int   ri[4], off[4];
#pragma unroll
    for (int j = 0; j < 4; ++j) {
        float4 lv = s_lv[lb + j];
        resF[j] = lv.x;
        ri[j]   = __float_as_int(lv.y);
        off[j]  = __float_as_int(lv.z);
    }

    int p0      = gid >> 2;
    int pstride = (gridDim.x * blockDim.x) >> 2;

#pragma unroll 2
    for (int p = p0; p < n_points; p += pstride) {
        // 4 consecutive threads read the same point -> broadcast load
        float2 xy = __ldg(((const float2*)x) + p);

        int   idx[4];
        float wx[4], wy[4];
#pragma unroll
        for (int j = 0; j < 4; ++j) {
            float px = xy.x * resF[j];
            float py = xy.y * resF[j];
            float fx = floorf(px);
            float fy = floorf(py);
            wx[j] = px - fx;
            wy[j] = py - fy;

            int ix = min(max((int)fx, 0), ri[j] - 1);
            int iy = min(max((int)fy, 0), ri[j] - 1);
            idx[j] = off[j] + iy * ri[j] + ix;
        }

        uint4 rr[4];
#pragma unroll
        for (int j = 0; j < 4; ++j) {
            if (lb + j < 7) {
                rr[j] = __ldg(&g_packed[idx[j]]);     // L1-resident coarse
            } else {
                uint4 v;
                asm("ld.global.cg.v4.u32 {%0,%1,%2,%3}, [%4];"
                    : "=r"(v.x), "=r"(v.y), "=r"(v.z), "=r"(v.w)
                    : "l"(&g_packed[idx[j]]));        // L2-only fine
                rr[j] = v;
            }
        }

        float o[8];
#pragma unroll
        for (int j = 0; j < 4; ++j) {
            float2 f00 = __half22float2(*(const half2*)&rr[j].x);
            float2 f10 = __half22float2(*(const half2*)&rr[j].y);
            float2 f01 = __half22float2(*(const half2*)&rr[j].z);
            float2 f11 = __half22float2(*(const half2*)&rr[j].w);

            float u = 1.0f - wx[j];
            float v = 1.0f - wy[j];

            o[2 * j]     = (f00.x * u + f10.x * wx[j]) * v + (f01.x * u + f11.x * wx[j]) * wy[j];
            o[2 * j + 1] = (f00.y * u + f10.y * wx[j]) * v + (f01.y * u + f11.y * wx[j]) * wy[j];
        }

        // 4 threads per point -> full 128B line; streaming (evict-first).
        float* dst = out + (size_t)p * (NLEV * 2) + lb * 2;
        asm volatile("st.global.cs.v4.f32 [%0], {%1,%2,%3,%4};"
                     :: "l"(dst), "f"(o[0]), "f"(o[1]), "f"(o[2]), "f"(o[3]));
        asm volatile("st.global.cs.v4.f32 [%0], {%1,%2,%3,%4};"
                     :: "l"(dst + 4), "f"(o[4]), "f"(o[5]), "f"(o[6]), "f"(o[7]));
    }
}

extern "C" void kernel_launch(void* const* d_in, const int* in_sizes, int n_in,
                              void* d_out, int out_size)
{
    const float* x   = (const float*)d_in[0];
    const float* emb = (const float*)d_in[1];
    float* out       = (float*)d_out;

    int n_points = in_sizes[0] / 2;

    Params pm;
    double b = exp((log(512.0) - log(16.0)) / 15.0);
    int acc = 0;
    for (int l = 0; l < NLEV; ++l) {
        double r = floor(16.0 * pow(b, (double)l));
        pm.resF[l] = (float)r;
        pm.resI[l] = (int)r;
        pm.off[l]  = acc;
        acc += pm.resI[l] * pm.resI[l];
    }
    pm.total = acc;

    static int nsm = 0;
    if (nsm == 0) {
        cudaDeviceGetAttribute(&nsm, cudaDevAttrMultiProcessorCount, 0);
        cudaFuncSetAttribute(hash_embed_kernel,
                             cudaFuncAttributePreferredSharedMemoryCarveout,
                             cudaSharedmemCarveoutMaxL1);
    }

    // Phase 1: build packed corner table (fp16, 16B per cell)
    {
        int threads = 256;
        int blocks = (acc + threads - 1) / threads;
        build_packed_kernel<<<blocks, threads>>>(emb, pm, acc);
    }

    // Phase 2: persistent gather + lerp (5 blocks/SM x 256 thr)
    {
        int blocks = nsm * 5;
        hash_embed_kernel<<<blocks, 256>>>(x, out, n_points, pm);
    }
}

// round 16
// speedup vs baseline: 1.4428x; 1.0183x over previous
#include <cuda_runtime.h>
#include <cuda_fp16.h>
#include <math.h>
#include <stdint.h>

// HashEmbedder: 16-level 2D multires hash grid, 2 feats/level, T=2^19.
// Phase 1: build fp16 cell-packed corner table (16B per cell).
// Phase 2: PERSISTENT double-buffered pipeline, 4 thr/point, 4 levels/thr.
//   - iteration i+1's xy-load + 4 gathers issued BEFORE iteration i's lerp
//     (structural overlap; no reliance on ptxas hoisting ld.cg over st.cs)
//   - level params in registers; levels 0-6 __ldg (L1, MaxL1 carveout),
//     7-15 ld.cg (L2-only); st.cs streaming stores.

#define NLEV 16
#define TLOG2 19
#define TSIZE (1u << TLOG2)
#define HMASK ((1u << TLOG2) - 1u)
#define PRIME1 2654435761u

// Sum of res^2 over the 16 levels = 706,816 cells; margin for safety.
#define MAX_CELLS 710000
__device__ uint4 g_packed[MAX_CELLS];   // 16B per cell: h00,h10,h01,h11

struct Params {
    float resF[NLEV];
    int   resI[NLEV];
    int   off[NLEV];
    int   total;
};

// ---------------------------------------------------------------------------
// Phase 1: build packed table. One thread per cell.
// ---------------------------------------------------------------------------
__global__ __launch_bounds__(256) void build_packed_kernel(
    const float* __restrict__ emb, Params pm, int total_cells)
{
    int i = blockIdx.x * blockDim.x + threadIdx.x;
    if (i >= total_cells) return;

    int l = 0;
#pragma unroll
    for (int k = 1; k < NLEV; ++k) l += (i >= pm.off[k]);

    int c   = i - pm.off[l];
    int res = pm.resI[l];
    int cy  = c / res;
    int cx  = c - cy * res;

    uint32_t ux0 = (uint32_t)cx;
    uint32_t ux1 = (uint32_t)(cx + 1);
    uint32_t yp0 = (uint32_t)cy * PRIME1;
    uint32_t yp1 = (uint32_t)(cy + 1) * PRIME1;

    uint32_t a00 = (ux0 ^ yp0) & HMASK;
    uint32_t a10 = (ux1 ^ yp0) & HMASK;
    uint32_t a01 = (ux0 ^ yp1) & HMASK;
    uint32_t a11 = (ux1 ^ yp1) & HMASK;

    const float2* __restrict__ tab =
        ((const float2*)emb) + ((size_t)l << TLOG2);

    float2 f00 = __ldg(tab + a00);
    float2 f10 = __ldg(tab + a10);
    float2 f01 = __ldg(tab + a01);
    float2 f11 = __ldg(tab + a11);

    half2 h00 = __float22half2_rn(f00);
    half2 h10 = __float22half2_rn(f10);
    half2 h01 = __float22half2_rn(f01);
    half2 h11 = __float22half2_rn(f11);

    uint4 r;
    r.x = *(const uint32_t*)&h00;
    r.y = *(const uint32_t*)&h10;
    r.z = *(const uint32_t*)&h01;
    r.w = *(const uint32_t*)&h11;
    g_packed[i] = r;
}

// ---------------------------------------------------------------------------
// Gather helpers
// ---------------------------------------------------------------------------
__device__ __forceinline__ void gather4(
    const float2& xy, const float* resF, const int* ri, const int* off,
    int lb, uint4* rr)
{
#pragma unroll
    for (int j = 0; j < 4; ++j) {
        float px = xy.x * resF[j];
        float py = xy.y * resF[j];
        int ix = min(max((int)floorf(px), 0), ri[j] - 1);
        int iy = min(max((int)floorf(py), 0), ri[j] - 1);
        int idx = off[j] + iy * ri[j] + ix;

        if (lb + j < 7) {
            rr[j] = __ldg(&g_packed[idx]);           // L1-resident coarse
        } else {
            uint4 v;
            asm("ld.global.cg.v4.u32 {%0,%1,%2,%3}, [%4];"
                : "=r"(v.x), "=r"(v.y), "=r"(v.z), "=r"(v.w)
                : "l"(&g_packed[idx]));              // L2-only fine
            rr[j] = v;
        }
    }
}

__device__ __forceinline__ void lerp_store(
    const float2& xy, const float* resF, const uint4* rr,
    float* __restrict__ out, int p, int lb)
{
    float o[8];
#pragma unroll
    for (int j = 0; j < 4; ++j) {
        float px = xy.x * resF[j];
        float py = xy.y * resF[j];
        float wx = px - floorf(px);
        float wy = py - floorf(py);

        float2 f00 = __half22float2(*(const half2*)&rr[j].x);
        float2 f10 = __half22float2(*(const half2*)&rr[j].y);
        float2 f01 = __half22float2(*(const half2*)&rr[j].z);
        float2 f11 = __half22float2(*(const half2*)&rr[j].w);

        float u = 1.0f - wx;
        float v = 1.0f - wy;

        o[2 * j]     = (f00.x * u + f10.x * wx) * v + (f01.x * u + f11.x * wx) * wy;
        o[2 * j + 1] = (f00.y * u + f10.y * wx) * v + (f01.y * u + f11.y * wx) * wy;
    }

    float* dst = out + (size_t)p * (NLEV * 2) + lb * 2;
    asm volatile("st.global.cs.v4.f32 [%0], {%1,%2,%3,%4};"
                 :: "l"(dst), "f"(o[0]), "f"(o[1]), "f"(o[2]), "f"(o[3]));
    asm volatile("st.global.cs.v4.f32 [%0], {%1,%2,%3,%4};"
                 :: "l"(dst + 4), "f"(o[4]), "f"(o[5]), "f"(o[6]), "f"(o[7]));
}

// ---------------------------------------------------------------------------
// Phase 2: persistent, double-buffered. 4 threads per point.
// ---------------------------------------------------------------------------
__global__ __launch_bounds__(256, 4) void hash_embed_kernel(
    const float* __restrict__ x,
    float* __restrict__ out,
    int n_points,
    Params pm)
{
    __shared__ float4 s_lv[NLEV];
    if (threadIdx.x < NLEV) {
        s_lv[threadIdx.x] = make_float4(
            pm.resF[threadIdx.x],
            __int_as_float(pm.resI[threadIdx.x]),
            __int_as_float(pm.off[threadIdx.x]),
            0.0f);
    }
    __syncthreads();

    int gid = blockIdx.x * blockDim.x + threadIdx.x;
    int lb  = (gid & 3) << 2;      // base level per thread: 0,4,8,12

    float resF[4];
    int   ri[4], off[4];
#pragma unroll
    for (int j = 0; j < 4; ++j) {
        float4 lv = s_lv[lb + j];
        resF[j] = lv.x;
        ri[j]   = __float_as_int(lv.y);
        off[j]  = __float_as_int(lv.z);
    }

    int p       = gid >> 2;
    int pstride = (gridDim.x * blockDim.x) >> 2;
    if (p >= n_points) return;

    // Prologue: issue point p's gathers
    float2 xy = __ldg(((const float2*)x) + p);
    uint4  rr[4];
    gather4(xy, resF, ri, off, lb, rr);

    // Steady state: issue next point's loads before consuming current
    for (;;) {
        int  pn   = p + pstride;
        bool more = pn < n_points;

        float2 xy2;
        uint4  rr2[4];
        if (more) {
            xy2 = __ldg(((const float2*)x) + pn);
            gather4(xy2, resF, ri, off, lb, rr2);
        }

        lerp_store(xy, resF, rr, out, p, lb);

        if (!more) break;
        p  = pn;
        xy = xy2;
#pragma unroll
        for (int j = 0; j < 4; ++j) rr[j] = rr2[j];
    }
}

extern "C" void kernel_launch(void* const* d_in, const int* in_sizes, int n_in,
                              void* d_out, int out_size)
{
    const float* x   = (const float*)d_in[0];
    const float* emb = (const float*)d_in[1];
    float* out       = (float*)d_out;

    int n_points = in_sizes[0] / 2;

    Params pm;
    double b = exp((log(512.0) - log(16.0)) / 15.0);
    int acc = 0;
    for (int l = 0; l < NLEV; ++l) {
        double r = floor(16.0 * pow(b, (double)l));
        pm.resF[l] = (float)r;
        pm.resI[l] = (int)r;
        pm.off[l]  = acc;
        acc += pm.resI[l] * pm.resI[l];
    }
    pm.total = acc;

    static int nsm = 0;
    if (nsm == 0) {
        cudaDeviceGetAttribute(&nsm, cudaDevAttrMultiProcessorCount, 0);
        cudaFuncSetAttribute(hash_embed_kernel,
                             cudaFuncAttributePreferredSharedMemoryCarveout,
                             cudaSharedmemCarveoutMaxL1);
    }

    // Phase 1: build packed corner table (fp16, 16B per cell)
    {
        int threads = 256;
        int blocks = (acc + threads - 1) / threads;
        build_packed_kernel<<<blocks, threads>>>(emb, pm, acc);
    }

    // Phase 2: persistent double-buffered gather + lerp
    {
        int blocks = nsm * 4;
        hash_embed_kernel<<<blocks, 256>>>(x, out, n_points, pm);
    }
}